// round 2
// baseline (speedup 1.0000x reference)
#include <cuda_runtime.h>
#include <math.h>

#define NN 100000
#define EE 1600000
#define HH 128
#define GG 64

// ---------- device scratch (allocation-free rule: static __device__ globals) ----------
__device__ int   g_degcnt[NN];
__device__ float g_dinv[NN];
__device__ int   g_rowptr[NN + 1];
__device__ int   g_cursor[NN];
__device__ int   g_colsrc[EE];
__device__ float g_bufA[(size_t)NN * HH];   // 51.2 MB
__device__ float g_bufB[(size_t)NN * HH];   // 51.2 MB
__device__ float g_sums[GG * HH];
__device__ int   g_cnt[GG];

// ---------- packed f32x2 helpers (sm_103a FFMA2: 2 fp32 FMA per instr) ----------
__device__ __forceinline__ unsigned long long pk2(float lo, float hi) {
    unsigned long long r;
    asm("mov.b64 %0, {%1, %2};" : "=l"(r) : "f"(lo), "f"(hi));
    return r;
}
__device__ __forceinline__ void upk2(unsigned long long v, float& lo, float& hi) {
    asm("mov.b64 {%0, %1}, %2;" : "=f"(lo), "=f"(hi) : "l"(v));
}
__device__ __forceinline__ unsigned long long fma2(unsigned long long a,
                                                   unsigned long long b,
                                                   unsigned long long c) {
    unsigned long long d;
    asm("fma.rn.f32x2 %0, %1, %2, %3;" : "=l"(d) : "l"(a), "l"(b), "l"(c));
    return d;
}

__device__ __forceinline__ float elu_f(float x) { return x > 0.f ? x : expm1f(x); }

// ---------- 1. zero scratch ----------
__global__ void k_init() {
    int i = blockIdx.x * blockDim.x + threadIdx.x;
    int stride = gridDim.x * blockDim.x;
    for (int j = i; j < NN; j += stride) g_degcnt[j] = 0;
    for (int j = i; j < GG * HH; j += stride) g_sums[j] = 0.f;
    for (int j = i; j < GG; j += stride) g_cnt[j] = 0;
}

// ---------- 2. in-degree histogram ----------
__global__ void k_hist(const int* __restrict__ dst) {
    int i = blockIdx.x * 256 + threadIdx.x;
    if (i < EE) atomicAdd(&g_degcnt[dst[i]], 1);
}

// ---------- 3. exclusive scan -> rowptr/cursor, and dinv ----------
__global__ void k_scan() {
    __shared__ int sm[1024];
    int tid = threadIdx.x;
    const int chunk = (NN + 1023) / 1024;
    int start = tid * chunk;
    int end = min(start + chunk, NN);
    int s = 0;
    for (int i = start; i < end; i++) s += g_degcnt[i];
    sm[tid] = s;
    __syncthreads();
    for (int off = 1; off < 1024; off <<= 1) {
        int v = 0;
        if (tid >= off) v = sm[tid - off];
        __syncthreads();
        sm[tid] += v;
        __syncthreads();
    }
    int run = sm[tid] - s;  // exclusive prefix
    for (int i = start; i < end; i++) {
        int d = g_degcnt[i];
        g_rowptr[i] = run;
        g_cursor[i] = run;
        g_dinv[i] = rsqrtf((float)(d + 1));   // +1 self loop; always >= 1
        run += d;
    }
    if (tid == 1023) g_rowptr[NN] = sm[1023];
}

// ---------- 4. counting-sort edges by dst ----------
__global__ void k_fill(const int* __restrict__ src, const int* __restrict__ dst) {
    int i = blockIdx.x * 256 + threadIdx.x;
    if (i < EE) {
        int d = dst[i];
        int pos = atomicAdd(&g_cursor[d], 1);
        g_colsrc[pos] = src[i];
    }
}

// ---------- 5. GEMM: out[r][c] = (sum_k A[r][k]*W[k][c]) * dinv[r] ----------
// BM=64 rows per block, full K=128, full N=128 cols. 128 threads, 8x8 per thread.
#define GEMM_SMEM ((64 * 132 + 128 * 128) * 4)
__global__ void __launch_bounds__(128) k_gemm(const float* __restrict__ A,
                                              const float* __restrict__ W,
                                              float* __restrict__ out) {
    extern __shared__ float smem[];
    float* As = smem;               // [64][132] padded
    float* Ws = smem + 64 * 132;    // [128][128]
    const int tid = threadIdx.x;
    const int tx = tid & 15;        // 16 col-groups of 8
    const int ty = tid >> 4;        // 8 row-groups of 8
    const int rowBase = blockIdx.x * 64;

    const float4* Ag4 = (const float4*)A;
    for (int i = tid; i < 64 * 32; i += 128) {
        int r = i >> 5, k4 = i & 31;
        int gr = rowBase + r;
        float4 v = make_float4(0.f, 0.f, 0.f, 0.f);
        if (gr < NN) v = Ag4[gr * 32 + k4];
        *(float4*)&As[r * 132 + k4 * 4] = v;
    }
    const float4* Wg4 = (const float4*)W;
    float4* Ws4 = (float4*)Ws;
    for (int i = tid; i < 4096; i += 128) Ws4[i] = Wg4[i];
    __syncthreads();

    unsigned long long acc[8][4];
#pragma unroll
    for (int j = 0; j < 8; j++)
#pragma unroll
        for (int i = 0; i < 4; i++) acc[j][i] = 0ULL;

    const int r0 = ty * 8;
#pragma unroll 4
    for (int k = 0; k < 128; k++) {
        float4 wA = Ws4[k * 32 + tx * 2];
        float4 wB = Ws4[k * 32 + tx * 2 + 1];
        unsigned long long w0 = pk2(wA.x, wA.y);
        unsigned long long w1 = pk2(wA.z, wA.w);
        unsigned long long w2 = pk2(wB.x, wB.y);
        unsigned long long w3 = pk2(wB.z, wB.w);
#pragma unroll
        for (int j = 0; j < 8; j++) {
            float a = As[(r0 + j) * 132 + k];
            unsigned long long aa = pk2(a, a);
            acc[j][0] = fma2(aa, w0, acc[j][0]);
            acc[j][1] = fma2(aa, w1, acc[j][1]);
            acc[j][2] = fma2(aa, w2, acc[j][2]);
            acc[j][3] = fma2(aa, w3, acc[j][3]);
        }
    }

#pragma unroll
    for (int j = 0; j < 8; j++) {
        int gr = rowBase + r0 + j;
        if (gr < NN) {
            float di = g_dinv[gr];
            float o[8];
            upk2(acc[j][0], o[0], o[1]);
            upk2(acc[j][1], o[2], o[3]);
            upk2(acc[j][2], o[4], o[5]);
            upk2(acc[j][3], o[6], o[7]);
            float4 v0 = make_float4(o[0] * di, o[1] * di, o[2] * di, o[3] * di);
            float4 v1 = make_float4(o[4] * di, o[5] * di, o[6] * di, o[7] * di);
            ((float4*)out)[gr * 32 + tx * 2] = v0;
            ((float4*)out)[gr * 32 + tx * 2 + 1] = v1;
        }
    }
}

// ---------- 6. aggregation: out[i] = elu(dinv[i] * (hs[i] + sum_{src in N(i)} hs[src]) + b) ----------
// one warp per node; lane holds a float4 column slice (32*4 = 128 cols)
__global__ void __launch_bounds__(256) k_agg(const float* __restrict__ hs,
                                             const float* __restrict__ b,
                                             float* __restrict__ out) {
    int warp = (blockIdx.x * blockDim.x + threadIdx.x) >> 5;
    int lane = threadIdx.x & 31;
    if (warp >= NN) return;
    const float4* hs4 = (const float4*)hs;
    float4 acc = hs4[(size_t)warp * 32 + lane];   // self loop term
    int e = g_rowptr[warp];
    int end = g_rowptr[warp + 1];
    for (; e + 4 <= end; e += 4) {
        int s0 = g_colsrc[e];
        int s1 = g_colsrc[e + 1];
        int s2 = g_colsrc[e + 2];
        int s3 = g_colsrc[e + 3];
        float4 v0 = hs4[(size_t)s0 * 32 + lane];
        float4 v1 = hs4[(size_t)s1 * 32 + lane];
        float4 v2 = hs4[(size_t)s2 * 32 + lane];
        float4 v3 = hs4[(size_t)s3 * 32 + lane];
        acc.x += (v0.x + v1.x) + (v2.x + v3.x);
        acc.y += (v0.y + v1.y) + (v2.y + v3.y);
        acc.z += (v0.z + v1.z) + (v2.z + v3.z);
        acc.w += (v0.w + v1.w) + (v2.w + v3.w);
    }
    for (; e < end; e++) {
        int s = g_colsrc[e];
        float4 v = hs4[(size_t)s * 32 + lane];
        acc.x += v.x; acc.y += v.y; acc.z += v.z; acc.w += v.w;
    }
    float di = g_dinv[warp];
    float4 bb = ((const float4*)b)[lane];
    float4 r;
    r.x = elu_f(acc.x * di + bb.x);
    r.y = elu_f(acc.y * di + bb.y);
    r.z = elu_f(acc.z * di + bb.z);
    r.w = elu_f(acc.w * di + bb.w);
    ((float4*)out)[(size_t)warp * 32 + lane] = r;
}

// ---------- 7. mean-pool partial sums (batch is sorted -> run-length accumulate) ----------
#define POOL_NPB 512
__global__ void k_pool(const float* __restrict__ act, const int* __restrict__ batch) {
    int col = threadIdx.x;   // 128 threads = 128 cols
    int start = blockIdx.x * POOL_NPB;
    if (start >= NN) return;
    int end = min(start + POOL_NPB, NN);
    float acc = 0.f;
    int cur = batch[start];
    int cl = 0;
    for (int i = start; i < end; i++) {
        int bb = batch[i];
        if (bb != cur) {
            atomicAdd(&g_sums[cur * HH + col], acc);
            if (col == 0) atomicAdd(&g_cnt[cur], cl);
            acc = 0.f; cl = 0; cur = bb;
        }
        acc += act[(size_t)i * HH + col];
        cl++;
    }
    atomicAdd(&g_sums[cur * HH + col], acc);
    if (col == 0) atomicAdd(&g_cnt[cur], cl);
}

// ---------- 8. classifier head: sigmoid(relu(g@Wc1+bc1)@Wc2+bc2) ----------
__global__ void k_mlp(const float* __restrict__ Wc1, const float* __restrict__ bc1,
                      const float* __restrict__ Wc2, const float* __restrict__ bc2,
                      float* __restrict__ out) {
    __shared__ float gs[GG][129];
    int tid = threadIdx.x;   // 256 threads
    for (int idx = tid; idx < GG * HH; idx += 256) {
        int g = idx >> 7, k = idx & 127;
        float c = fmaxf((float)g_cnt[g], 1.f);
        gs[g][k] = g_sums[idx] / c;
    }
    __syncthreads();
    int gid = tid >> 2;     // graph
    int q = tid & 3;        // 4 threads per graph, 16 hidden units each
    float part = 0.f;
    for (int j = q * 16; j < q * 16 + 16; j++) {
        float z = bc1[j];
#pragma unroll 4
        for (int k = 0; k < 128; k++) z += gs[gid][k] * Wc1[k * 64 + j];
        part += fmaxf(z, 0.f) * Wc2[j];
    }
    part += __shfl_down_sync(0xffffffffu, part, 2);
    part += __shfl_down_sync(0xffffffffu, part, 1);
    if (q == 0) out[gid] = 1.f / (1.f + expf(-(part + bc2[0])));
}

// ---------- launch ----------
extern "C" void kernel_launch(void* const* d_in, const int* in_sizes, int n_in,
                              void* d_out, int out_size) {
    const float* x   = (const float*)d_in[0];
    const int*   ei  = (const int*)d_in[1];
    const int*   bat = (const int*)d_in[2];
    const float* W1  = (const float*)d_in[3];
    const float* b1  = (const float*)d_in[4];
    const float* W2  = (const float*)d_in[5];
    const float* b2  = (const float*)d_in[6];
    const float* W3  = (const float*)d_in[7];
    const float* b3  = (const float*)d_in[8];
    const float* Wc1 = (const float*)d_in[9];
    const float* bc1 = (const float*)d_in[10];
    const float* Wc2 = (const float*)d_in[11];
    const float* bc2 = (const float*)d_in[12];
    float* out = (float*)d_out;

    const int* src = ei;        // edge_index[0]
    const int* dst = ei + EE;   // edge_index[1]

    cudaFuncSetAttribute(k_gemm, cudaFuncAttributeMaxDynamicSharedMemorySize, GEMM_SMEM);

    void *pA, *pB;
    cudaGetSymbolAddress(&pA, g_bufA);
    cudaGetSymbolAddress(&pB, g_bufB);
    float* bufA = (float*)pA;
    float* bufB = (float*)pB;

    k_init<<<391, 256>>>();
    k_hist<<<(EE + 255) / 256, 256>>>(dst);
    k_scan<<<1, 1024>>>();
    k_fill<<<(EE + 255) / 256, 256>>>(src, dst);

    const int gemm_grid = (NN + 63) / 64;
    const int agg_grid  = (NN + 7) / 8;

    k_gemm<<<gemm_grid, 128, GEMM_SMEM>>>(x, W1, bufA);
    k_agg<<<agg_grid, 256>>>(bufA, b1, bufB);
    k_gemm<<<gemm_grid, 128, GEMM_SMEM>>>(bufB, W2, bufA);
    k_agg<<<agg_grid, 256>>>(bufA, b2, bufB);
    k_gemm<<<gemm_grid, 128, GEMM_SMEM>>>(bufB, W3, bufA);
    k_agg<<<agg_grid, 256>>>(bufA, b3, bufB);

    k_pool<<<(NN + POOL_NPB - 1) / POOL_NPB, 128>>>(bufB, bat);
    k_mlp<<<1, 256>>>(Wc1, bc1, Wc2, bc2, out);
}

// round 4
// speedup vs baseline: 1.1291x; 1.1291x over previous
#include <cuda_runtime.h>
#include <cuda_bf16.h>
#include <math.h>

#define NN 100000
#define EE 1600000
#define HH 128
#define GG 64

// ---------- device scratch (allocation-free rule: static __device__ globals) ----------
__device__ int   g_degcnt[NN];
__device__ float g_dinv[NN];
__device__ int   g_rowptr[NN + 1];
__device__ int   g_cursor[NN];
__device__ int   g_colsrc[EE];
__device__ __align__(16) __nv_bfloat16 g_bufA[(size_t)NN * HH];   // 25.6 MB
__device__ __align__(16) __nv_bfloat16 g_bufB[(size_t)NN * HH];   // 25.6 MB
__device__ float g_sums[GG * HH];
__device__ int   g_cnt[GG];

// ---------- packed f32x2 helpers (sm_103a FFMA2: 2 fp32 FMA per instr) ----------
__device__ __forceinline__ unsigned long long pk2(float lo, float hi) {
    unsigned long long r;
    asm("mov.b64 %0, {%1, %2};" : "=l"(r) : "f"(lo), "f"(hi));
    return r;
}
__device__ __forceinline__ void upk2(unsigned long long v, float& lo, float& hi) {
    asm("mov.b64 {%0, %1}, %2;" : "=f"(lo), "=f"(hi) : "l"(v));
}
__device__ __forceinline__ unsigned long long fma2(unsigned long long a,
                                                   unsigned long long b,
                                                   unsigned long long c) {
    unsigned long long d;
    asm("fma.rn.f32x2 %0, %1, %2, %3;" : "=l"(d) : "l"(a), "l"(b), "l"(c));
    return d;
}

__device__ __forceinline__ float2 bf2f(unsigned int v) {
    __nv_bfloat162 b = *reinterpret_cast<__nv_bfloat162*>(&v);
    return __bfloat1622float2(b);
}
__device__ __forceinline__ unsigned int f2bf(float a, float b) {
    __nv_bfloat162 r = __float22bfloat162_rn(make_float2(a, b));
    return *reinterpret_cast<unsigned int*>(&r);
}

__device__ __forceinline__ float elu_f(float x) { return x > 0.f ? x : expm1f(x); }

// ---------- 1. zero scratch ----------
__global__ void k_init() {
    int i = blockIdx.x * blockDim.x + threadIdx.x;
    int stride = gridDim.x * blockDim.x;
    for (int j = i; j < NN; j += stride) g_degcnt[j] = 0;
    for (int j = i; j < GG * HH; j += stride) g_sums[j] = 0.f;
    for (int j = i; j < GG; j += stride) g_cnt[j] = 0;
}

// ---------- 2. in-degree histogram ----------
__global__ void k_hist(const int* __restrict__ dst) {
    int i = blockIdx.x * 256 + threadIdx.x;
    if (i < EE) atomicAdd(&g_degcnt[dst[i]], 1);
}

// ---------- 3. exclusive scan -> rowptr/cursor, and dinv ----------
__global__ void k_scan() {
    __shared__ int sm[1024];
    int tid = threadIdx.x;
    const int chunk = (NN + 1023) / 1024;
    int start = tid * chunk;
    int end = min(start + chunk, NN);
    int s = 0;
    for (int i = start; i < end; i++) s += g_degcnt[i];
    sm[tid] = s;
    __syncthreads();
    for (int off = 1; off < 1024; off <<= 1) {
        int v = 0;
        if (tid >= off) v = sm[tid - off];
        __syncthreads();
        sm[tid] += v;
        __syncthreads();
    }
    int run = sm[tid] - s;  // exclusive prefix
    for (int i = start; i < end; i++) {
        int d = g_degcnt[i];
        g_rowptr[i] = run;
        g_cursor[i] = run;
        g_dinv[i] = rsqrtf((float)(d + 1));   // +1 self loop; always >= 1
        run += d;
    }
    if (tid == 1023) g_rowptr[NN] = sm[1023];
}

// ---------- 4. counting-sort edges by dst ----------
__global__ void k_fill(const int* __restrict__ src, const int* __restrict__ dst) {
    int i = blockIdx.x * 256 + threadIdx.x;
    if (i < EE) {
        int d = dst[i];
        int pos = atomicAdd(&g_cursor[d], 1);
        g_colsrc[pos] = src[i];
    }
}

// ---------- 5. GEMM (fp32 A input, layer 1): out_bf16[r][c] = (A[r]·W[:,c]) * dinv[r] ----------
#define GEMM_SMEM ((64 * 132 + 128 * 128) * 4)
__global__ void __launch_bounds__(128) k_gemm_f32(const float* __restrict__ A,
                                                  const float* __restrict__ W,
                                                  __nv_bfloat16* __restrict__ out) {
    extern __shared__ float smem[];
    float* As = smem;               // [64][132] padded
    float* Ws = smem + 64 * 132;    // [128][128]
    const int tid = threadIdx.x;
    const int tx = tid & 15;        // 16 col-groups of 8
    const int ty = tid >> 4;        // 8 row-groups of 8
    const int rowBase = blockIdx.x * 64;

    const float4* Ag4 = (const float4*)A;
    for (int i = tid; i < 64 * 32; i += 128) {
        int r = i >> 5, k4 = i & 31;
        int gr = rowBase + r;
        float4 v = make_float4(0.f, 0.f, 0.f, 0.f);
        if (gr < NN) v = Ag4[(size_t)gr * 32 + k4];
        *(float4*)&As[r * 132 + k4 * 4] = v;
    }
    const float4* Wg4 = (const float4*)W;
    float4* Ws4 = (float4*)Ws;
    for (int i = tid; i < 4096; i += 128) Ws4[i] = Wg4[i];
    __syncthreads();

    unsigned long long acc[8][4];
#pragma unroll
    for (int j = 0; j < 8; j++)
#pragma unroll
        for (int i = 0; i < 4; i++) acc[j][i] = 0ULL;

    const int r0 = ty * 8;
#pragma unroll 4
    for (int k = 0; k < 128; k++) {
        float4 wA = Ws4[k * 32 + tx * 2];
        float4 wB = Ws4[k * 32 + tx * 2 + 1];
        unsigned long long w0 = pk2(wA.x, wA.y);
        unsigned long long w1 = pk2(wA.z, wA.w);
        unsigned long long w2 = pk2(wB.x, wB.y);
        unsigned long long w3 = pk2(wB.z, wB.w);
#pragma unroll
        for (int j = 0; j < 8; j++) {
            float a = As[(r0 + j) * 132 + k];
            unsigned long long aa = pk2(a, a);
            acc[j][0] = fma2(aa, w0, acc[j][0]);
            acc[j][1] = fma2(aa, w1, acc[j][1]);
            acc[j][2] = fma2(aa, w2, acc[j][2]);
            acc[j][3] = fma2(aa, w3, acc[j][3]);
        }
    }

#pragma unroll
    for (int j = 0; j < 8; j++) {
        int gr = rowBase + r0 + j;
        if (gr < NN) {
            float di = g_dinv[gr];
            float o[8];
            upk2(acc[j][0], o[0], o[1]);
            upk2(acc[j][1], o[2], o[3]);
            upk2(acc[j][2], o[4], o[5]);
            upk2(acc[j][3], o[6], o[7]);
            uint4 st;
            st.x = f2bf(o[0] * di, o[1] * di);
            st.y = f2bf(o[2] * di, o[3] * di);
            st.z = f2bf(o[4] * di, o[5] * di);
            st.w = f2bf(o[6] * di, o[7] * di);
            ((uint4*)out)[(size_t)gr * 16 + tx] = st;   // row = 128 bf16 = 16 uint4
        }
    }
}

// ---------- 5b. GEMM (bf16 A input, layers 2/3) ----------
__global__ void __launch_bounds__(128) k_gemm_bf16(const __nv_bfloat16* __restrict__ A,
                                                   const float* __restrict__ W,
                                                   __nv_bfloat16* __restrict__ out) {
    extern __shared__ float smem[];
    float* As = smem;               // [64][132] padded fp32
    float* Ws = smem + 64 * 132;    // [128][128]
    const int tid = threadIdx.x;
    const int tx = tid & 15;
    const int ty = tid >> 4;
    const int rowBase = blockIdx.x * 64;

    // load bf16 A rows, convert to fp32 in smem. 64 rows x 16 uint4 = 1024 chunks.
    for (int i = tid; i < 1024; i += 128) {
        int r = i >> 4, c = i & 15;
        int gr = rowBase + r;
        uint4 v = make_uint4(0u, 0u, 0u, 0u);
        if (gr < NN) v = ((const uint4*)A)[(size_t)gr * 16 + c];
        float2 f0 = bf2f(v.x), f1 = bf2f(v.y), f2 = bf2f(v.z), f3 = bf2f(v.w);
        float* dp = &As[r * 132 + c * 8];
        *(float4*)(dp)     = make_float4(f0.x, f0.y, f1.x, f1.y);
        *(float4*)(dp + 4) = make_float4(f2.x, f2.y, f3.x, f3.y);
    }
    const float4* Wg4 = (const float4*)W;
    float4* Ws4 = (float4*)(smem + 64 * 132);
    for (int i = tid; i < 4096; i += 128) Ws4[i] = Wg4[i];
    __syncthreads();

    unsigned long long acc[8][4];
#pragma unroll
    for (int j = 0; j < 8; j++)
#pragma unroll
        for (int i = 0; i < 4; i++) acc[j][i] = 0ULL;

    const int r0 = ty * 8;
#pragma unroll 4
    for (int k = 0; k < 128; k++) {
        float4 wA = Ws4[k * 32 + tx * 2];
        float4 wB = Ws4[k * 32 + tx * 2 + 1];
        unsigned long long w0 = pk2(wA.x, wA.y);
        unsigned long long w1 = pk2(wA.z, wA.w);
        unsigned long long w2 = pk2(wB.x, wB.y);
        unsigned long long w3 = pk2(wB.z, wB.w);
#pragma unroll
        for (int j = 0; j < 8; j++) {
            float a = As[(r0 + j) * 132 + k];
            unsigned long long aa = pk2(a, a);
            acc[j][0] = fma2(aa, w0, acc[j][0]);
            acc[j][1] = fma2(aa, w1, acc[j][1]);
            acc[j][2] = fma2(aa, w2, acc[j][2]);
            acc[j][3] = fma2(aa, w3, acc[j][3]);
        }
    }

#pragma unroll
    for (int j = 0; j < 8; j++) {
        int gr = rowBase + r0 + j;
        if (gr < NN) {
            float di = g_dinv[gr];
            float o[8];
            upk2(acc[j][0], o[0], o[1]);
            upk2(acc[j][1], o[2], o[3]);
            upk2(acc[j][2], o[4], o[5]);
            upk2(acc[j][3], o[6], o[7]);
            uint4 st;
            st.x = f2bf(o[0] * di, o[1] * di);
            st.y = f2bf(o[2] * di, o[3] * di);
            st.z = f2bf(o[4] * di, o[5] * di);
            st.w = f2bf(o[6] * di, o[7] * di);
            ((uint4*)out)[(size_t)gr * 16 + tx] = st;
        }
    }
}

// ---------- 6. aggregation over bf16 rows (fp32 accumulate) ----------
// one warp per node; lane holds 4 bf16 cols (uint2 = 8B -> 32 lanes = 256B row)
__global__ void __launch_bounds__(256) k_agg(const __nv_bfloat16* __restrict__ hs,
                                             const float* __restrict__ b,
                                             __nv_bfloat16* __restrict__ out) {
    int warp = (blockIdx.x * blockDim.x + threadIdx.x) >> 5;
    int lane = threadIdx.x & 31;
    if (warp >= NN) return;
    const uint2* hs2 = (const uint2*)hs;

    uint2 sv = hs2[(size_t)warp * 32 + lane];     // self-loop term
    float2 s0 = bf2f(sv.x), s1 = bf2f(sv.y);
    float4 acc = make_float4(s0.x, s0.y, s1.x, s1.y);

    int e = g_rowptr[warp];
    int end = g_rowptr[warp + 1];
    for (; e + 4 <= end; e += 4) {
        int n0 = g_colsrc[e];
        int n1 = g_colsrc[e + 1];
        int n2 = g_colsrc[e + 2];
        int n3 = g_colsrc[e + 3];
        uint2 v0 = hs2[(size_t)n0 * 32 + lane];
        uint2 v1 = hs2[(size_t)n1 * 32 + lane];
        uint2 v2 = hs2[(size_t)n2 * 32 + lane];
        uint2 v3 = hs2[(size_t)n3 * 32 + lane];
        float2 a0 = bf2f(v0.x), b0 = bf2f(v0.y);
        float2 a1 = bf2f(v1.x), b1 = bf2f(v1.y);
        float2 a2 = bf2f(v2.x), b2 = bf2f(v2.y);
        float2 a3 = bf2f(v3.x), b3 = bf2f(v3.y);
        acc.x += (a0.x + a1.x) + (a2.x + a3.x);
        acc.y += (a0.y + a1.y) + (a2.y + a3.y);
        acc.z += (b0.x + b1.x) + (b2.x + b3.x);
        acc.w += (b0.y + b1.y) + (b2.y + b3.y);
    }
    for (; e < end; e++) {
        int s = g_colsrc[e];
        uint2 v = hs2[(size_t)s * 32 + lane];
        float2 a = bf2f(v.x), c = bf2f(v.y);
        acc.x += a.x; acc.y += a.y; acc.z += c.x; acc.w += c.y;
    }
    float di = g_dinv[warp];
    float4 bb = ((const float4*)b)[lane];
    uint2 st;
    st.x = f2bf(elu_f(acc.x * di + bb.x), elu_f(acc.y * di + bb.y));
    st.y = f2bf(elu_f(acc.z * di + bb.z), elu_f(acc.w * di + bb.w));
    ((uint2*)out)[(size_t)warp * 32 + lane] = st;
}

// ---------- 7. mean-pool partial sums (batch is sorted -> run-length accumulate) ----------
#define POOL_NPB 512
__global__ void k_pool(const __nv_bfloat16* __restrict__ act, const int* __restrict__ batch) {
    int col = threadIdx.x;   // 128 threads = 128 cols
    int start = blockIdx.x * POOL_NPB;
    if (start >= NN) return;
    int end = min(start + POOL_NPB, NN);
    float acc = 0.f;
    int cur = batch[start];
    int cl = 0;
    for (int i = start; i < end; i++) {
        int bb = batch[i];
        if (bb != cur) {
            atomicAdd(&g_sums[cur * HH + col], acc);
            if (col == 0) atomicAdd(&g_cnt[cur], cl);
            acc = 0.f; cl = 0; cur = bb;
        }
        acc += __bfloat162float(act[(size_t)i * HH + col]);
        cl++;
    }
    atomicAdd(&g_sums[cur * HH + col], acc);
    if (col == 0) atomicAdd(&g_cnt[cur], cl);
}

// ---------- 8. classifier head: sigmoid(relu(g@Wc1+bc1)@Wc2+bc2) ----------
__global__ void k_mlp(const float* __restrict__ Wc1, const float* __restrict__ bc1,
                      const float* __restrict__ Wc2, const float* __restrict__ bc2,
                      float* __restrict__ out) {
    __shared__ float gs[GG][129];
    int tid = threadIdx.x;   // 256 threads
    for (int idx = tid; idx < GG * HH; idx += 256) {
        int g = idx >> 7, k = idx & 127;
        float c = fmaxf((float)g_cnt[g], 1.f);
        gs[g][k] = g_sums[idx] / c;
    }
    __syncthreads();
    int gid = tid >> 2;     // graph
    int q = tid & 3;        // 4 threads per graph, 16 hidden units each
    float part = 0.f;
    for (int j = q * 16; j < q * 16 + 16; j++) {
        float z = bc1[j];
#pragma unroll 4
        for (int k = 0; k < 128; k++) z += gs[gid][k] * Wc1[k * 64 + j];
        part += fmaxf(z, 0.f) * Wc2[j];
    }
    part += __shfl_down_sync(0xffffffffu, part, 2);
    part += __shfl_down_sync(0xffffffffu, part, 1);
    if (q == 0) out[gid] = 1.f / (1.f + expf(-(part + bc2[0])));
}

// ---------- launch ----------
extern "C" void kernel_launch(void* const* d_in, const int* in_sizes, int n_in,
                              void* d_out, int out_size) {
    const float* x   = (const float*)d_in[0];
    const int*   ei  = (const int*)d_in[1];
    const int*   bat = (const int*)d_in[2];
    const float* W1  = (const float*)d_in[3];
    const float* b1  = (const float*)d_in[4];
    const float* W2  = (const float*)d_in[5];
    const float* b2  = (const float*)d_in[6];
    const float* W3  = (const float*)d_in[7];
    const float* b3  = (const float*)d_in[8];
    const float* Wc1 = (const float*)d_in[9];
    const float* bc1 = (const float*)d_in[10];
    const float* Wc2 = (const float*)d_in[11];
    const float* bc2 = (const float*)d_in[12];
    float* out = (float*)d_out;

    const int* src = ei;        // edge_index[0]
    const int* dst = ei + EE;   // edge_index[1]

    cudaFuncSetAttribute(k_gemm_f32, cudaFuncAttributeMaxDynamicSharedMemorySize, GEMM_SMEM);
    cudaFuncSetAttribute(k_gemm_bf16, cudaFuncAttributeMaxDynamicSharedMemorySize, GEMM_SMEM);

    void *pA, *pB;
    cudaGetSymbolAddress(&pA, g_bufA);
    cudaGetSymbolAddress(&pB, g_bufB);
    __nv_bfloat16* bufA = (__nv_bfloat16*)pA;
    __nv_bfloat16* bufB = (__nv_bfloat16*)pB;

    k_init<<<391, 256>>>();
    k_hist<<<(EE + 255) / 256, 256>>>(dst);
    k_scan<<<1, 1024>>>();
    k_fill<<<(EE + 255) / 256, 256>>>(src, dst);

    const int gemm_grid = (NN + 63) / 64;
    const int agg_grid  = (NN + 7) / 8;

    k_gemm_f32 <<<gemm_grid, 128, GEMM_SMEM>>>(x, W1, bufA);
    k_agg<<<agg_grid, 256>>>(bufA, b1, bufB);
    k_gemm_bf16<<<gemm_grid, 128, GEMM_SMEM>>>(bufB, W2, bufA);
    k_agg<<<agg_grid, 256>>>(bufA, b2, bufB);
    k_gemm_bf16<<<gemm_grid, 128, GEMM_SMEM>>>(bufB, W3, bufA);
    k_agg<<<agg_grid, 256>>>(bufA, b3, bufB);

    k_pool<<<(NN + POOL_NPB - 1) / POOL_NPB, 128>>>(bufB, bat);
    k_mlp<<<1, 256>>>(Wc1, bc1, Wc2, bc2, out);
}

// round 7
// speedup vs baseline: 1.3876x; 1.2290x over previous
#include <cuda_runtime.h>
#include <cuda_bf16.h>
#include <math.h>

#define NN 100000
#define EE 1600000
#define HH 128
#define GG 64

// ---------- device scratch ----------
__device__ int   g_degcnt[NN];
__device__ float g_dinv[NN];
__device__ int   g_rowptr[NN + 1];
__device__ int   g_cursor[NN];
__device__ int   g_colsrc[EE];
__device__ __align__(16) __nv_bfloat16 g_bufA[(size_t)NN * HH];
__device__ __align__(16) __nv_bfloat16 g_bufB[(size_t)NN * HH];
__device__ __align__(16) __nv_bfloat16 g_bufX[(size_t)NN * HH];
__device__ __align__(16) __nv_bfloat16 g_whi[3][HH * HH];   // Wt_hi[n][k]
__device__ __align__(16) __nv_bfloat16 g_wlo[3][HH * HH];   // Wt_lo[n][k]
__device__ float g_sums[GG * HH];
__device__ int   g_cnt[GG];

// ---------- helpers ----------
__device__ __forceinline__ float2 bf2f(unsigned int v) {
    __nv_bfloat162 b = *reinterpret_cast<__nv_bfloat162*>(&v);
    return __bfloat1622float2(b);
}
__device__ __forceinline__ unsigned int f2bf(float a, float b) {
    __nv_bfloat162 r = __float22bfloat162_rn(make_float2(a, b));
    return *reinterpret_cast<unsigned int*>(&r);
}
__device__ __forceinline__ float elu_f(float x) { return x > 0.f ? x : expm1f(x); }

__device__ __forceinline__ unsigned int smem_u32(const void* p) {
    unsigned int a;
    asm("{ .reg .u64 t; cvta.to.shared.u64 t, %1; cvt.u32.u64 %0, t; }" : "=r"(a) : "l"(p));
    return a;
}

// ---------- 1. zero scratch ----------
__global__ void k_init() {
    int i = blockIdx.x * blockDim.x + threadIdx.x;
    int stride = gridDim.x * blockDim.x;
    for (int j = i; j < NN; j += stride) g_degcnt[j] = 0;
    for (int j = i; j < GG * HH; j += stride) g_sums[j] = 0.f;
    for (int j = i; j < GG; j += stride) g_cnt[j] = 0;
}

// ---------- 2. in-degree histogram ----------
__global__ void k_hist(const int* __restrict__ dst) {
    int i = blockIdx.x * 256 + threadIdx.x;
    if (i < EE) atomicAdd(&g_degcnt[dst[i]], 1);
}

// ---------- 3. scan -> rowptr/cursor/dinv ----------
__global__ void k_scan() {
    __shared__ int sm[1024];
    int tid = threadIdx.x;
    const int chunk = (NN + 1023) / 1024;
    int start = tid * chunk;
    int end = min(start + chunk, NN);
    int s = 0;
    for (int i = start; i < end; i++) s += g_degcnt[i];
    sm[tid] = s;
    __syncthreads();
    for (int off = 1; off < 1024; off <<= 1) {
        int v = 0;
        if (tid >= off) v = sm[tid - off];
        __syncthreads();
        sm[tid] += v;
        __syncthreads();
    }
    int run = sm[tid] - s;
    for (int i = start; i < end; i++) {
        int d = g_degcnt[i];
        g_rowptr[i] = run;
        g_cursor[i] = run;
        g_dinv[i] = rsqrtf((float)(d + 1));
        run += d;
    }
    if (tid == 1023) g_rowptr[NN] = sm[1023];
}

// ---------- 4. counting-sort edges by dst ----------
__global__ void k_fill(const int* __restrict__ src, const int* __restrict__ dst) {
    int i = blockIdx.x * 256 + threadIdx.x;
    if (i < EE) {
        int d = dst[i];
        int pos = atomicAdd(&g_cursor[d], 1);
        g_colsrc[pos] = src[i];
    }
}

// ---------- 4b. convert x -> bf16 ----------
__global__ void k_prepx(const float* __restrict__ x) {
    int i = blockIdx.x * blockDim.x + threadIdx.x;
    int stride = gridDim.x * blockDim.x;
    const int total = NN * HH / 2;
    unsigned int* out = (unsigned int*)g_bufX;
    const float2* in = (const float2*)x;
    for (int j = i; j < total; j += stride) {
        float2 v = in[j];
        out[j] = f2bf(v.x, v.y);
    }
}

// ---------- 4c. transpose + split weights: Wt_hi/Wt_lo[n][k] ----------
__global__ void k_prepw(const float* __restrict__ W1, const float* __restrict__ W2,
                        const float* __restrict__ W3) {
    int i = blockIdx.x * 256 + threadIdx.x;
    if (i >= 3 * HH * HH) return;
    int w = i / (HH * HH);
    int j = i % (HH * HH);
    int n = j >> 7, k = j & 127;
    const float* Wp = (w == 0) ? W1 : (w == 1) ? W2 : W3;
    float v = Wp[k * HH + n];
    __nv_bfloat16 hi = __float2bfloat16(v);
    float lo = v - __bfloat162float(hi);
    g_whi[w][n * HH + k] = hi;
    g_wlo[w][n * HH + k] = __float2bfloat16(lo);
}

// ---------- 5. HMMA GEMM: out[r][c] = (sum_k A[r][k]*W[k][c]) * dinv[r] ----------
// CTA = 128 rows x 128 cols x K=128, 8 warps, warp = 16 rows x 128 cols.
// mma.sync.m16n8k16 bf16 -> f32; W = Whi + Wlo (split bf16) for fp32-grade weights.
// smem rows padded to 272 B (17x16B): ldmatrix rows land on distinct bank groups.
#define ROWB 272
#define SM_WH 34816
#define SM_WL 69632
#define GT_SMEM 104448
__global__ void __launch_bounds__(256) k_gemm_mma(const __nv_bfloat16* __restrict__ A,
                                                  const __nv_bfloat16* __restrict__ Whi,
                                                  const __nv_bfloat16* __restrict__ Wlo,
                                                  __nv_bfloat16* __restrict__ out) {
    extern __shared__ char smem[];
    const int tid = threadIdx.x;
    const int wid = tid >> 5;
    const int lane = tid & 31;
    const int rowBase = blockIdx.x * 128;

    // stage A (zero-filled OOB) + Whi + Wlo
    const uint4* Ag = (const uint4*)A;
    const uint4* Wh = (const uint4*)Whi;
    const uint4* Wl = (const uint4*)Wlo;
    const uint4 z4 = make_uint4(0u, 0u, 0u, 0u);
    for (int i = tid; i < 2048; i += 256) {
        int r = i >> 4, c = i & 15;
        int gr = rowBase + r;
        uint4 v = (gr < NN) ? Ag[(size_t)gr * 16 + c] : z4;
        *(uint4*)(smem + r * ROWB + c * 16) = v;
        *(uint4*)(smem + SM_WH + r * ROWB + c * 16) = Wh[i];
        *(uint4*)(smem + SM_WL + r * ROWB + c * 16) = Wl[i];
    }
    __syncthreads();

    unsigned int sb = smem_u32(smem);
    const int R = wid * 16;

    float acc[16][4];
#pragma unroll
    for (int nb = 0; nb < 16; nb++)
#pragma unroll
        for (int j = 0; j < 4; j++) acc[nb][j] = 0.f;

    // ldmatrix base addresses
    unsigned int aBase = sb + (R + (lane & 15)) * ROWB + (lane >> 4) * 16;
    unsigned int bRow = (lane & 7) * ROWB + ((lane >> 3) & 1) * 16;
    unsigned int bhBase = sb + SM_WH + bRow;
    unsigned int blBase = sb + SM_WL + bRow;

#pragma unroll
    for (int ks = 0; ks < 8; ks++) {
        unsigned int a0, a1, a2, a3;
        asm volatile("ldmatrix.sync.aligned.m8n8.x4.shared.b16 {%0,%1,%2,%3}, [%4];"
                     : "=r"(a0), "=r"(a1), "=r"(a2), "=r"(a3)
                     : "r"(aBase + ks * 32));
#pragma unroll
        for (int nb = 0; nb < 16; nb++) {
            unsigned int b0, b1;
            asm volatile("ldmatrix.sync.aligned.m8n8.x2.shared.b16 {%0,%1}, [%2];"
                         : "=r"(b0), "=r"(b1)
                         : "r"(bhBase + nb * (8 * ROWB) + ks * 32));
            asm volatile("mma.sync.aligned.m16n8k16.row.col.f32.bf16.bf16.f32 "
                         "{%0,%1,%2,%3}, {%4,%5,%6,%7}, {%8,%9}, {%0,%1,%2,%3};"
                         : "+f"(acc[nb][0]), "+f"(acc[nb][1]), "+f"(acc[nb][2]), "+f"(acc[nb][3])
                         : "r"(a0), "r"(a1), "r"(a2), "r"(a3), "r"(b0), "r"(b1));
            asm volatile("ldmatrix.sync.aligned.m8n8.x2.shared.b16 {%0,%1}, [%2];"
                         : "=r"(b0), "=r"(b1)
                         : "r"(blBase + nb * (8 * ROWB) + ks * 32));
            asm volatile("mma.sync.aligned.m16n8k16.row.col.f32.bf16.bf16.f32 "
                         "{%0,%1,%2,%3}, {%4,%5,%6,%7}, {%8,%9}, {%0,%1,%2,%3};"
                         : "+f"(acc[nb][0]), "+f"(acc[nb][1]), "+f"(acc[nb][2]), "+f"(acc[nb][3])
                         : "r"(a0), "r"(a1), "r"(a2), "r"(a3), "r"(b0), "r"(b1));
        }
    }

    // epilogue: D frag (r, c)=(R+lane/4, nb*8+(lane%4)*2): d0,d1 row r; d2,d3 row r+8
    int r0 = rowBase + R + (lane >> 2);
    int r1 = r0 + 8;
    float d0 = (r0 < NN) ? g_dinv[r0] : 0.f;
    float d1 = (r1 < NN) ? g_dinv[r1] : 0.f;
    unsigned int colHalf = (lane & 3) * 2;
#pragma unroll
    for (int nb = 0; nb < 16; nb++) {
        unsigned int c = nb * 8 + colHalf;
        if (r0 < NN)
            *(unsigned int*)&out[(size_t)r0 * HH + c] = f2bf(acc[nb][0] * d0, acc[nb][1] * d0);
        if (r1 < NN)
            *(unsigned int*)&out[(size_t)r1 * HH + c] = f2bf(acc[nb][2] * d1, acc[nb][3] * d1);
    }
}

// ---------- 6. aggregation (bf16 rows, fp32 accum), MLP=8 ----------
__global__ void __launch_bounds__(256) k_agg(const __nv_bfloat16* __restrict__ hs,
                                             const float* __restrict__ b,
                                             __nv_bfloat16* __restrict__ out) {
    int warp = (blockIdx.x * blockDim.x + threadIdx.x) >> 5;
    int lane = threadIdx.x & 31;
    if (warp >= NN) return;
    const uint2* hs2 = (const uint2*)hs;

    uint2 sv = hs2[(size_t)warp * 32 + lane];
    float2 s0 = bf2f(sv.x), s1 = bf2f(sv.y);
    float4 acc = make_float4(s0.x, s0.y, s1.x, s1.y);

    int e = g_rowptr[warp];
    int end = g_rowptr[warp + 1];
    for (; e + 8 <= end; e += 8) {
        int n0 = g_colsrc[e + 0], n1 = g_colsrc[e + 1];
        int n2 = g_colsrc[e + 2], n3 = g_colsrc[e + 3];
        int n4 = g_colsrc[e + 4], n5 = g_colsrc[e + 5];
        int n6 = g_colsrc[e + 6], n7 = g_colsrc[e + 7];
        uint2 v0 = hs2[(size_t)n0 * 32 + lane];
        uint2 v1 = hs2[(size_t)n1 * 32 + lane];
        uint2 v2 = hs2[(size_t)n2 * 32 + lane];
        uint2 v3 = hs2[(size_t)n3 * 32 + lane];
        uint2 v4 = hs2[(size_t)n4 * 32 + lane];
        uint2 v5 = hs2[(size_t)n5 * 32 + lane];
        uint2 v6 = hs2[(size_t)n6 * 32 + lane];
        uint2 v7 = hs2[(size_t)n7 * 32 + lane];
        float2 a0 = bf2f(v0.x), c0 = bf2f(v0.y);
        float2 a1 = bf2f(v1.x), c1 = bf2f(v1.y);
        float2 a2 = bf2f(v2.x), c2 = bf2f(v2.y);
        float2 a3 = bf2f(v3.x), c3 = bf2f(v3.y);
        float2 a4 = bf2f(v4.x), c4 = bf2f(v4.y);
        float2 a5 = bf2f(v5.x), c5 = bf2f(v5.y);
        float2 a6 = bf2f(v6.x), c6 = bf2f(v6.y);
        float2 a7 = bf2f(v7.x), c7 = bf2f(v7.y);
        acc.x += ((a0.x + a1.x) + (a2.x + a3.x)) + ((a4.x + a5.x) + (a6.x + a7.x));
        acc.y += ((a0.y + a1.y) + (a2.y + a3.y)) + ((a4.y + a5.y) + (a6.y + a7.y));
        acc.z += ((c0.x + c1.x) + (c2.x + c3.x)) + ((c4.x + c5.x) + (c6.x + c7.x));
        acc.w += ((c0.y + c1.y) + (c2.y + c3.y)) + ((c4.y + c5.y) + (c6.y + c7.y));
    }
    for (; e < end; e++) {
        int s = g_colsrc[e];
        uint2 v = hs2[(size_t)s * 32 + lane];
        float2 a = bf2f(v.x), c = bf2f(v.y);
        acc.x += a.x; acc.y += a.y; acc.z += c.x; acc.w += c.y;
    }
    float di = g_dinv[warp];
    float4 bb = ((const float4*)b)[lane];
    uint2 st;
    st.x = f2bf(elu_f(acc.x * di + bb.x), elu_f(acc.y * di + bb.y));
    st.y = f2bf(elu_f(acc.z * di + bb.z), elu_f(acc.w * di + bb.w));
    ((uint2*)out)[(size_t)warp * 32 + lane] = st;
}

// ---------- 7. mean-pool ----------
#define POOL_NPB 512
__global__ void k_pool(const __nv_bfloat16* __restrict__ act, const int* __restrict__ batch) {
    int col = threadIdx.x;
    int start = blockIdx.x * POOL_NPB;
    if (start >= NN) return;
    int end = min(start + POOL_NPB, NN);
    float acc = 0.f;
    int cur = batch[start];
    int cl = 0;
    for (int i = start; i < end; i++) {
        int bb = batch[i];
        if (bb != cur) {
            atomicAdd(&g_sums[cur * HH + col], acc);
            if (col == 0) atomicAdd(&g_cnt[cur], cl);
            acc = 0.f; cl = 0; cur = bb;
        }
        acc += __bfloat162float(act[(size_t)i * HH + col]);
        cl++;
    }
    atomicAdd(&g_sums[cur * HH + col], acc);
    if (col == 0) atomicAdd(&g_cnt[cur], cl);
}

// ---------- 8. classifier head ----------
__global__ void k_mlp(const float* __restrict__ Wc1, const float* __restrict__ bc1,
                      const float* __restrict__ Wc2, const float* __restrict__ bc2,
                      float* __restrict__ out) {
    __shared__ float gs[GG][129];
    int tid = threadIdx.x;
    for (int idx = tid; idx < GG * HH; idx += 256) {
        int g = idx >> 7, k = idx & 127;
        float c = fmaxf((float)g_cnt[g], 1.f);
        gs[g][k] = g_sums[idx] / c;
    }
    __syncthreads();
    int gid = tid >> 2;
    int q = tid & 3;
    float part = 0.f;
    for (int j = q * 16; j < q * 16 + 16; j++) {
        float z = bc1[j];
#pragma unroll 4
        for (int k = 0; k < 128; k++) z += gs[gid][k] * Wc1[k * 64 + j];
        part += fmaxf(z, 0.f) * Wc2[j];
    }
    part += __shfl_down_sync(0xffffffffu, part, 2);
    part += __shfl_down_sync(0xffffffffu, part, 1);
    if (q == 0) out[gid] = 1.f / (1.f + expf(-(part + bc2[0])));
}

// ---------- launch ----------
extern "C" void kernel_launch(void* const* d_in, const int* in_sizes, int n_in,
                              void* d_out, int out_size) {
    const float* x   = (const float*)d_in[0];
    const int*   ei  = (const int*)d_in[1];
    const int*   bat = (const int*)d_in[2];
    const float* W1  = (const float*)d_in[3];
    const float* b1  = (const float*)d_in[4];
    const float* W2  = (const float*)d_in[5];
    const float* b2  = (const float*)d_in[6];
    const float* W3  = (const float*)d_in[7];
    const float* b3  = (const float*)d_in[8];
    const float* Wc1 = (const float*)d_in[9];
    const float* bc1 = (const float*)d_in[10];
    const float* Wc2 = (const float*)d_in[11];
    const float* bc2 = (const float*)d_in[12];
    float* out = (float*)d_out;

    const int* src = ei;
    const int* dst = ei + EE;

    cudaFuncSetAttribute(k_gemm_mma, cudaFuncAttributeMaxDynamicSharedMemorySize, GT_SMEM);

    void *pA, *pB, *pX, *pWh, *pWl;
    cudaGetSymbolAddress(&pA, g_bufA);
    cudaGetSymbolAddress(&pB, g_bufB);
    cudaGetSymbolAddress(&pX, g_bufX);
    cudaGetSymbolAddress(&pWh, g_whi);
    cudaGetSymbolAddress(&pWl, g_wlo);
    __nv_bfloat16* bufA = (__nv_bfloat16*)pA;
    __nv_bfloat16* bufB = (__nv_bfloat16*)pB;
    __nv_bfloat16* bufX = (__nv_bfloat16*)pX;
    __nv_bfloat16* whi = (__nv_bfloat16*)pWh;
    __nv_bfloat16* wlo = (__nv_bfloat16*)pWl;

    k_init<<<391, 256>>>();
    k_hist<<<(EE + 255) / 256, 256>>>(dst);
    k_scan<<<1, 1024>>>();
    k_fill<<<(EE + 255) / 256, 256>>>(src, dst);
    k_prepx<<<1024, 256>>>(x);
    k_prepw<<<192, 256>>>(W1, W2, W3);

    const int gemm_grid = (NN + 127) / 128;
    const int agg_grid  = (NN + 7) / 8;

    k_gemm_mma<<<gemm_grid, 256, GT_SMEM>>>(bufX, whi, wlo, bufA);
    k_agg<<<agg_grid, 256>>>(bufA, b1, bufB);
    k_gemm_mma<<<gemm_grid, 256, GT_SMEM>>>(bufB, whi + HH * HH, wlo + HH * HH, bufA);
    k_agg<<<agg_grid, 256>>>(bufA, b2, bufB);
    k_gemm_mma<<<gemm_grid, 256, GT_SMEM>>>(bufB, whi + 2 * HH * HH, wlo + 2 * HH * HH, bufA);
    k_agg<<<agg_grid, 256>>>(bufA, b3, bufB);

    k_pool<<<(NN + POOL_NPB - 1) / POOL_NPB, 128>>>(bufB, bat);
    k_mlp<<<1, 256>>>(Wc1, bc1, Wc2, bc2, out);
}